// round 15
// baseline (speedup 1.0000x reference)
#include <cuda_runtime.h>
#include <math.h>
#include <stdint.h>

__device__ int g_tile_counter;   // reset to 0 by kernel_launch each call

namespace {

constexpr int Bc = 32, Nc = 96, Dc = 32, Fc = 16;
constexpr int THREADS = 512;        // four independent 128-thread streams
constexpr int SWIDTH  = 128;
constexpr int NSTREAM = 4;
constexpr int GRID    = 152;        // persistent: 1 CTA per SM
constexpr int NTILES  = Bc * Nc;    // 3072
constexpr int NSTREAMS_TOTAL = GRID * NSTREAM;   // 608
constexpr int EPAD    = 20;
constexpr int ECAP    = 64;         // staged-row cap (overflow handled scalar)

// Shared (read-only after init)
constexpr int OFF_WFRAG = 0;                 // float4[128 nt][32 lane] = 65536
constexpr int OFF_BIAS  = 65536;             // 1024 f = 4096
constexpr int OFF_WIH   = 69632;             // w_ih^T [32][96] = 12288
constexpr int OFF_WHH   = 81920;             // w_hh^T [32][96] = 12288
// Per-stream block (double-buffered E/mn)
constexpr int OFF_S0  = 94208;
constexpr int SO_E0   = 0;       // 64 x 20 u32 = 5120
constexpr int SO_E1   = 5120;
constexpr int SO_MN0  = 10240;   // 1024 float2 = 8192
constexpr int SO_MN1  = 18432;
constexpr int SO_ACT  = 26624;   // [4][96] int = 1536
constexpr int SO_X1   = 28160;   // [4][32] f = 512
constexpr int SO_CNT  = 28672;   // [4] int
constexpr int SO_TILE = 28688;   // [4] int
constexpr int SO_AGG  = 28704;   // [2][32] f = 256
constexpr int SO_GI   = 28960;   // 96 f
constexpr int SO_GH   = 29344;   // 96 f
constexpr int SO_H1   = 29728;   // 32 f -> 29856
constexpr int S_BYTES = 29952;
constexpr int SMEM_BYTES = OFF_S0 + NSTREAM * S_BYTES;   // 214016

__device__ __forceinline__ float sigmoidf_(float x) { return 1.0f / (1.0f + expf(-x)); }

__device__ __forceinline__ uint32_t f2tf32(float x) {
    uint32_t r;
    asm("cvt.rna.tf32.f32 %0, %1;" : "=r"(r) : "f"(x));
    return r;
}

__device__ __forceinline__ void mma_tf32(float& d0, float& d1, float& d2, float& d3,
                                         uint32_t a0, uint32_t a1, uint32_t a2, uint32_t a3,
                                         uint32_t b0, uint32_t b1) {
    asm volatile(
        "mma.sync.aligned.m16n8k8.row.col.f32.tf32.tf32.f32 "
        "{%0,%1,%2,%3}, {%4,%5,%6,%7}, {%8,%9}, {%0,%1,%2,%3};"
        : "+f"(d0), "+f"(d1), "+f"(d2), "+f"(d3)
        : "r"(a0), "r"(a1), "r"(a2), "r"(a3), "r"(b0), "r"(b1));
}

// mn storage (64-row buffer, 8 e-blocks):
// (e,qp) -> float2 slot = ((qp>>2)*8 + (e>>3))*32 + (qp&3)*8 + (e&7)
__device__ __forceinline__ int mn_idx(int e, int qp) {
    return (((qp >> 2) * 8 + (e >> 3)) << 5) + ((qp & 3) << 3) + (e & 7);
}

__device__ __forceinline__ void stream_bar(int s) {
    asm volatile("bar.sync %0, %1;" :: "r"(s + 1), "r"(SWIDTH) : "memory");
}

// Warp-collective: compact active edges of tile t into slot p; stage x1.
__device__ __forceinline__ void compact_tile(int t, int p, int lane,
                                             const float* __restrict__ mask,
                                             const float* __restrict__ nodes,
                                             int* act_sh, int* cnt_sh, float* x1_sh) {
    const int b = t / Nc;
    const int i = t - b * Nc;
    const size_t mbase = (size_t)b * (Nc * Nc) + (size_t)i * Nc;
    int cnt = 0;
#pragma unroll
    for (int rr = 0; rr < Nc / 32; rr++) {
        const int j = rr * 32 + lane;
        const bool a = (mask[mbase + j] != 0.0f);
        const unsigned bal = __ballot_sync(0xffffffffu, a);
        if (a) act_sh[p * 96 + cnt + __popc(bal & ((1u << lane) - 1u))] = j;
        cnt += __popc(bal);
    }
    if (lane == 0) cnt_sh[p] = cnt;
    x1_sh[p * 32 + lane] = nodes[((size_t)b * Nc + i) * Dc + lane];
}

// mn staging via cp.async: all 128 threads, fire-and-forget.
__device__ __forceinline__ void stage_mn_cpasync(uint32_t mn_u32,
        const float* __restrict__ nodes, size_t nbase,
        const int* __restrict__ act, int cn, int padcnt, int tids) {
    for (int idx = tids; idx < padcnt * 16; idx += SWIDTH) {
        const int a  = idx >> 4;
        const int qp = idx & 15;
        const uint32_t dst = mn_u32 + (uint32_t)(mn_idx(a, qp) << 3);
        const float* src = (a < cn) ? (nodes + nbase + (size_t)act[a] * Dc + qp * 2)
                                    : nodes;
        const int sz = (a < cn) ? 8 : 0;     // sz=0 -> zero-fill 8 bytes
        asm volatile("cp.async.ca.shared.global [%0], [%1], 8, %2;"
                     :: "r"(dst), "l"(src), "r"(sz) : "memory");
    }
}

// E staging (tf32 cvt path), warps 0-2 only (tids in [0,96)).
__device__ __forceinline__ void stage_E(uint32_t* __restrict__ E_sh,
        const float* __restrict__ edges, size_t ebase,
        const int* __restrict__ act, int cn, int padcnt, int tids) {
    for (int idx = tids; idx < padcnt * 4; idx += 96) {
        const int a  = idx >> 2;
        const int f4 = (idx & 3) << 2;
        uint4 o = make_uint4(0u, 0u, 0u, 0u);
        if (a < cn) {
            const float4 v = *reinterpret_cast<const float4*>(
                edges + ebase + (size_t)act[a] * Fc + f4);
            o.x = f2tf32(v.x); o.y = f2tf32(v.y);
            o.z = f2tf32(v.z); o.w = f2tf32(v.w);
        }
        *reinterpret_cast<uint4*>(E_sh + a * EPAD + f4) = o;
    }
}

// Warp-collective GRU for one tile (warp 3 of each stream only).
__device__ __forceinline__ void gru_tile(int ptile, int lane,
                                         const float* x1p, const float* aggp,
                                         float* gi_sh, float* gh_sh, float* h1_sh,
                                         const float* wihT, const float* whhT,
                                         const float* __restrict__ b_ih,
                                         const float* __restrict__ b_hh,
                                         float* __restrict__ out) {
    const int pb = ptile / Nc;
    const int pi = ptile - pb * Nc;
#pragma unroll
    for (int g3 = 0; g3 < 3; g3++) {
        const int gate = g3 * 32 + lane;
        float g = b_ih[gate];
#pragma unroll
        for (int d = 0; d < Dc; d++) g = fmaf(x1p[d], wihT[d * 96 + gate], g);
        gi_sh[gate] = g;
    }
    __syncwarp();
    {
        const float r = sigmoidf_(gi_sh[lane] + b_hh[lane]);
        const float z = sigmoidf_(gi_sh[32 + lane] + b_hh[32 + lane]);
        const float n = tanhf(gi_sh[64 + lane] + r * b_hh[64 + lane]);
        h1_sh[lane] = (1.0f - z) * n;   // + z*h0, h0 = 0
    }
    __syncwarp();
#pragma unroll
    for (int g3 = 0; g3 < 3; g3++) {
        const int gate = g3 * 32 + lane;
        float g  = b_ih[gate];
        float gh = b_hh[gate];
#pragma unroll
        for (int d = 0; d < Dc; d++) {
            g  = fmaf(aggp[d],  wihT[d * 96 + gate], g);
            gh = fmaf(h1_sh[d], whhT[d * 96 + gate], gh);
        }
        gi_sh[gate] = g;
        gh_sh[gate] = gh;
    }
    __syncwarp();
    {
        const float r = sigmoidf_(gi_sh[lane] + gh_sh[lane]);
        const float z = sigmoidf_(gi_sh[32 + lane] + gh_sh[32 + lane]);
        const float n = tanhf(gi_sh[64 + lane] + r * gh_sh[64 + lane]);
        out[((size_t)pb * Nc + pi) * Dc + lane] = (1.0f - z) * n + z * h1_sh[lane];
    }
}

// Scalar fallback for cnt > ECAP (statistically never runs; kept for correctness).
__device__ void overflow_fix(int ptile, const int* __restrict__ act, int cntreal,
                             int lane, const float* __restrict__ edges,
                             const float* __restrict__ nodes,
                             const float* __restrict__ W_agg,
                             const float* __restrict__ b_agg, float* aggp) {
    const int pb = ptile / Nc;
    const int pi = ptile - pb * Nc;
    const size_t ebase = ((size_t)pb * (Nc * Nc) + (size_t)pi * Nc) * Fc;
    const size_t nbase = (size_t)pb * (Nc * Dc);
    for (int a = ECAP; a < cntreal; a++) {
        const int j = act[a];
        float e[16];
#pragma unroll
        for (int f = 0; f < 16; f++) e[f] = edges[ebase + (size_t)j * Fc + f];
        const float mnv = nodes[nbase + (size_t)j * Dc + lane];
        for (int p = 0; p < 32; p++) {
            const int pq = p * 32 + lane;
            float sv = b_agg[pq];
#pragma unroll
            for (int f = 0; f < 16; f++) sv = fmaf(e[f], W_agg[f * 1024 + pq], sv);
            float c = fmaxf(sv, 0.0f) * mnv;
#pragma unroll
            for (int o = 16; o; o >>= 1) c += __shfl_xor_sync(0xffffffffu, c, o);
            if (lane == 0) aggp[p] += c;
        }
    }
}

__global__ __launch_bounds__(THREADS, 1)
void mp_layer_kernel(const float* __restrict__ nodes,   // [B, N, D]
                     const float* __restrict__ edges,   // [B, N*N, F]
                     const float* __restrict__ mask,    // [B, N*N, 1] (0/1)
                     const float* __restrict__ W_agg,   // [F, D*D]
                     const float* __restrict__ b_agg,   // [D*D]
                     const float* __restrict__ w_ih,    // [3D, D]
                     const float* __restrict__ w_hh,    // [3D, D]
                     const float* __restrict__ b_ih,    // [3D]
                     const float* __restrict__ b_hh,    // [3D]
                     float* __restrict__ out)           // [B, N, D]
{
    extern __shared__ char smem[];
    float4* wfrag4  = reinterpret_cast<float4*>(smem + OFF_WFRAG);
    float*  bias_sh = reinterpret_cast<float*>(smem + OFF_BIAS);
    float*  wihT    = reinterpret_cast<float*>(smem + OFF_WIH);
    float*  whhT    = reinterpret_cast<float*>(smem + OFF_WHH);

    const int tid = threadIdx.x;

    // ---- One-time per CTA: W fragments (tf32, both k-steps packed), bias,
    //      transposed GRU weights ----
    for (int idx = tid; idx < 128 * 32; idx += THREADS) {
        const int l  = idx & 31;
        const int nt = idx >> 5;
        const int col = nt * 8 + (l >> 2);
        const int k   = l & 3;
        float4 v;
        v.x = __uint_as_float(f2tf32(W_agg[(k)      * 1024 + col]));
        v.y = __uint_as_float(f2tf32(W_agg[(k + 4)  * 1024 + col]));
        v.z = __uint_as_float(f2tf32(W_agg[(k + 8)  * 1024 + col]));
        v.w = __uint_as_float(f2tf32(W_agg[(k + 12) * 1024 + col]));
        wfrag4[idx] = v;
    }
    for (int c = tid; c < 1024; c += THREADS) bias_sh[c] = b_agg[c];
    for (int idx = tid; idx < 96 * 32; idx += THREADS) {
        const int g = idx >> 5;
        const int d = idx & 31;
        wihT[d * 96 + g] = w_ih[idx];
        whhT[d * 96 + g] = w_hh[idx];
    }
    __syncthreads();

    // ---- Stream-local views ----
    const int s    = tid >> 7;          // stream 0..3
    const int tids = tid & (SWIDTH - 1);
    const int lane = tid & 31;
    const int wq   = (tid >> 5) & 3;

    char* sbase = smem + OFF_S0 + s * S_BYTES;
    uint32_t* E0     = reinterpret_cast<uint32_t*>(sbase + SO_E0);
    uint32_t* E1     = reinterpret_cast<uint32_t*>(sbase + SO_E1);
    float2*   MN0    = reinterpret_cast<float2*>(sbase + SO_MN0);
    float2*   MN1    = reinterpret_cast<float2*>(sbase + SO_MN1);
    int*      act_sh = reinterpret_cast<int*>(sbase + SO_ACT);
    float*    x1_sh  = reinterpret_cast<float*>(sbase + SO_X1);
    int*      cnt_sh = reinterpret_cast<int*>(sbase + SO_CNT);
    int*      tile_sh= reinterpret_cast<int*>(sbase + SO_TILE);
    float*    agg_sh = reinterpret_cast<float*>(sbase + SO_AGG);
    float*    gi_sh  = reinterpret_cast<float*>(sbase + SO_GI);
    float*    gh_sh  = reinterpret_cast<float*>(sbase + SO_GH);
    float*    h1_sh  = reinterpret_cast<float*>(sbase + SO_H1);

    const uint32_t mn0_u32 = (uint32_t)__cvta_generic_to_shared(MN0);
    const uint32_t mn1_u32 = (uint32_t)__cvta_generic_to_shared(MN1);

    const int gsid = blockIdx.x * NSTREAM + s;

    // ---- Prologue: compact T0 (static) and T1 (dynamic); stage T0 -> buf0 ----
    if (wq == 3) {
        if (lane == 0) tile_sh[0] = gsid;
        compact_tile(gsid, 0, lane, mask, nodes, act_sh, cnt_sh, x1_sh);
        int t1;
        if (lane == 0) t1 = NSTREAMS_TOTAL + atomicAdd(&g_tile_counter, 1);
        t1 = __shfl_sync(0xffffffffu, t1, 0);
        if (lane == 0) tile_sh[1] = t1;
        if (t1 < NTILES) compact_tile(t1, 1, lane, mask, nodes, act_sh, cnt_sh, x1_sh);
    }
    stream_bar(s);
    {
        const int t0  = tile_sh[0];
        const int cn0 = min(cnt_sh[0], ECAP);
        const int pad0 = ((cn0 + 15) >> 4) << 4;
        const int b0 = t0 / Nc, i0 = t0 - b0 * Nc;
        stage_mn_cpasync(mn0_u32, nodes, (size_t)b0 * (Nc * Dc), act_sh, cn0, pad0, tids);
        asm volatile("cp.async.commit_group;" ::: "memory");
        if (wq < 3)
            stage_E(E0, edges, ((size_t)b0 * (Nc * Nc) + (size_t)i0 * Nc) * Fc,
                    act_sh, cn0, pad0, tids);
        asm volatile("cp.async.wait_group 0;" ::: "memory");
    }
    stream_bar(s);

    // Lane constants for the mainloop
    const int l4   = lane & 3;
    const int lr   = lane >> 2;
    const int mnlo = (l4 << 3) + (lr & 7);

    // ---- Pipelined dynamic tile loop ----
    int it = 0;
    while (true) {
        const int cur  = tile_sh[it & 3];
        const int prev = (it > 0) ? tile_sh[(it - 1) & 3] : NTILES;
        if (cur >= NTILES && prev >= NTILES) break;
        const bool valid = (cur < NTILES);
        const int par = it & 1;

        // ---- MMA(t) + reduce (data already resident in buf[par]) ----
        if (valid) {
            const int cn     = min(cnt_sh[it & 3], ECAP);
            const int mtiles = (cn + 15) >> 4;
            uint32_t* E_sh = par ? E1 : E0;
            float2*   mnS  = par ? MN1 : MN0;

            float acc[8] = {0.f, 0.f, 0.f, 0.f, 0.f, 0.f, 0.f, 0.f};
            int mt = 0;
            for (; mt + 2 <= mtiles; mt += 2) {
                const int r0 = mt * 16 + lr;
                const uint32_t* e0p = E_sh + r0 * EPAD;
                const uint32_t a00 = e0p[l4],            a01 = e0p[8*EPAD + l4];
                const uint32_t a02 = e0p[l4 + 4],        a03 = e0p[8*EPAD + l4 + 4];
                const uint32_t a10 = e0p[l4 + 8],        a11 = e0p[8*EPAD + l4 + 8];
                const uint32_t a12 = e0p[l4 + 12],       a13 = e0p[8*EPAD + l4 + 12];
                const uint32_t b00 = e0p[16*EPAD + l4],      b01 = e0p[24*EPAD + l4];
                const uint32_t b02 = e0p[16*EPAD + l4 + 4],  b03 = e0p[24*EPAD + l4 + 4];
                const uint32_t b10 = e0p[16*EPAD + l4 + 8],  b11 = e0p[24*EPAD + l4 + 8];
                const uint32_t b12 = e0p[16*EPAD + l4 + 12], b13 = e0p[24*EPAD + l4 + 12];
                const int blk0 = mt * 2;

#pragma unroll
                for (int c = 0; c < 4; c++) {
                    const float2* mp = mnS + ((c * 8 + blk0) << 5) + mnlo;
                    const float2 m0 = mp[0];
                    const float2 m1 = mp[32];
                    const float2 m2 = mp[64];
                    const float2 m3 = mp[96];
                    const float4* wp = wfrag4 + (wq * 32 + c) * 32 + lane;
                    const float2* bp = reinterpret_cast<const float2*>(
                        bias_sh + wq * 256 + c * 8 + l4 * 2);
#pragma unroll
                    for (int tsub = 0; tsub < 8; tsub++) {
                        const float4 bf = *wp;  wp += 128;
                        const float2 bb = *bp;  bp += 16;
                        float d0 = bb.x, d1 = bb.y, d2 = bb.x, d3 = bb.y;
                        float f0 = bb.x, f1 = bb.y, f2 = bb.x, f3 = bb.y;
                        mma_tf32(d0, d1, d2, d3, a00, a01, a02, a03,
                                 __float_as_uint(bf.x), __float_as_uint(bf.y));
                        mma_tf32(d0, d1, d2, d3, a10, a11, a12, a13,
                                 __float_as_uint(bf.z), __float_as_uint(bf.w));
                        mma_tf32(f0, f1, f2, f3, b00, b01, b02, b03,
                                 __float_as_uint(bf.x), __float_as_uint(bf.y));
                        mma_tf32(f0, f1, f2, f3, b10, b11, b12, b13,
                                 __float_as_uint(bf.z), __float_as_uint(bf.w));
                        d0 = fmaxf(d0, 0.0f); d1 = fmaxf(d1, 0.0f);
                        d2 = fmaxf(d2, 0.0f); d3 = fmaxf(d3, 0.0f);
                        f0 = fmaxf(f0, 0.0f); f1 = fmaxf(f1, 0.0f);
                        f2 = fmaxf(f2, 0.0f); f3 = fmaxf(f3, 0.0f);
                        float v = fmaf(d0, m0.x, fmaf(d1, m0.y,
                                  fmaf(d2, m1.x, fmaf(d3, m1.y, acc[tsub]))));
                        acc[tsub] = fmaf(f0, m2.x, fmaf(f1, m2.y,
                                    fmaf(f2, m3.x, fmaf(f3, m3.y, v))));
                    }
                }
            }
            if (mt < mtiles) {   // single-block tail (odd mtiles)
                const int r0 = mt * 16 + lr;
                const uint32_t* e0p = E_sh + r0 * EPAD;
                const uint32_t a00 = e0p[l4],      a01 = e0p[8*EPAD + l4];
                const uint32_t a02 = e0p[l4 + 4],  a03 = e0p[8*EPAD + l4 + 4];
                const uint32_t a10 = e0p[l4 + 8],  a11 = e0p[8*EPAD + l4 + 8];
                const uint32_t a12 = e0p[l4 + 12], a13 = e0p[8*EPAD + l4 + 12];
                const int blk0 = mt * 2;
#pragma unroll
                for (int c = 0; c < 4; c++) {
                    const float2* mp = mnS + ((c * 8 + blk0) << 5) + mnlo;
                    const float2 m0 = mp[0];
                    const float2 m1 = mp[32];
                    const float4* wp = wfrag4 + (wq * 32 + c) * 32 + lane;
                    const float2* bp = reinterpret_cast<const float2*>(
                        bias_sh + wq * 256 + c * 8 + l4 * 2);
#pragma unroll
                    for (int tsub = 0; tsub < 8; tsub++) {
                        const float4 bf = *wp;  wp += 128;
                        const float2 bb = *bp;  bp += 16;
                        float d0 = bb.x, d1 = bb.y, d2 = bb.x, d3 = bb.y;
                        mma_tf32(d0, d1, d2, d3, a00, a01, a02, a03,
                                 __float_as_uint(bf.x), __float_as_uint(bf.y));
                        mma_tf32(d0, d1, d2, d3, a10, a11, a12, a13,
                                 __float_as_uint(bf.z), __float_as_uint(bf.w));
                        d0 = fmaxf(d0, 0.0f); d1 = fmaxf(d1, 0.0f);
                        d2 = fmaxf(d2, 0.0f); d3 = fmaxf(d3, 0.0f);
                        acc[tsub] = fmaf(d0, m0.x, fmaf(d1, m0.y,
                                    fmaf(d2, m1.x, fmaf(d3, m1.y, acc[tsub]))));
                    }
                }
            }
            // Warp-reduce -> agg[par][wq*8 + pi]
#pragma unroll
            for (int pi = 0; pi < 8; pi++) {
                float v = acc[pi];
#pragma unroll
                for (int o = 16; o; o >>= 1) v += __shfl_xor_sync(0xffffffffu, v, o);
                if (lane == 0) agg_sh[par * 32 + wq * 8 + pi] = v;
            }
        }
        stream_bar(s);   // agg(t) published; buf[(t+1)&1] free for staging

        // ---- Overlap phase: stage(t+1) [cp.async + E], GRU(t-1), compact(t+2) ----
        {
            const int nxt_tile = tile_sh[(it + 1) & 3];
            if (nxt_tile < NTILES) {
                const int sslot = (it + 1) & 3;
                const int scn   = min(cnt_sh[sslot], ECAP);
                const int spad  = ((scn + 15) >> 4) << 4;
                const int sb = nxt_tile / Nc, si = nxt_tile - sb * Nc;
                const uint32_t mn_u32 = ((it + 1) & 1) ? mn1_u32 : mn0_u32;
                stage_mn_cpasync(mn_u32, nodes, (size_t)sb * (Nc * Dc),
                                 act_sh + sslot * 96, scn, spad, tids);
                asm volatile("cp.async.commit_group;" ::: "memory");
                if (wq < 3) {
                    uint32_t* sE = ((it + 1) & 1) ? E1 : E0;
                    stage_E(sE, edges,
                            ((size_t)sb * (Nc * Nc) + (size_t)si * Nc) * Fc,
                            act_sh + sslot * 96, scn, spad, tids);
                }
            }
        }
        if (wq == 3) {
            if (prev < NTILES) {
                const int pslot = (it - 1) & 3;
                const int pcnt  = cnt_sh[pslot];
                float* aggp = agg_sh + ((it - 1) & 1) * 32;
                if (pcnt > ECAP)
                    overflow_fix(prev, act_sh + pslot * 96, pcnt, lane,
                                 edges, nodes, W_agg, b_agg, aggp);
                gru_tile(prev, lane, x1_sh + pslot * 32, aggp,
                         gi_sh, gh_sh, h1_sh, wihT, whhT, b_ih, b_hh, out);
            }
            const int fslot = (it + 2) & 3;
            if (valid) {
                int nxt;
                if (lane == 0) nxt = NSTREAMS_TOTAL + atomicAdd(&g_tile_counter, 1);
                nxt = __shfl_sync(0xffffffffu, nxt, 0);
                if (lane == 0) tile_sh[fslot] = nxt;
                if (nxt < NTILES)
                    compact_tile(nxt, fslot, lane, mask, nodes, act_sh, cnt_sh, x1_sh);
            } else {
                if (lane == 0) tile_sh[fslot] = NTILES;
            }
        }
        asm volatile("cp.async.wait_group 0;" ::: "memory");
        stream_bar(s);   // staged buf visible; meta for t+1/t+2 visible
        it++;
    }
}

} // namespace

extern "C" void kernel_launch(void* const* d_in, const int* in_sizes, int n_in,
                              void* d_out, int out_size) {
    const float* nodes = (const float*)d_in[0];
    const float* edges = (const float*)d_in[1];
    const float* mask  = (const float*)d_in[2];
    const float* W_agg = (const float*)d_in[3];
    const float* b_agg = (const float*)d_in[4];
    const float* w_ih  = (const float*)d_in[5];
    const float* w_hh  = (const float*)d_in[6];
    const float* b_ih  = (const float*)d_in[7];
    const float* b_hh  = (const float*)d_in[8];
    float* out = (float*)d_out;

    void* ctr = nullptr;
    cudaGetSymbolAddress(&ctr, g_tile_counter);
    cudaMemsetAsync(ctr, 0, sizeof(int));

    cudaFuncSetAttribute(mp_layer_kernel,
                         cudaFuncAttributeMaxDynamicSharedMemorySize, SMEM_BYTES);
    mp_layer_kernel<<<GRID, THREADS, SMEM_BYTES>>>(nodes, edges, mask, W_agg, b_agg,
                                                   w_ih, w_hh, b_ih, b_hh, out);
}

// round 16
// speedup vs baseline: 1.2631x; 1.2631x over previous
#include <cuda_runtime.h>
#include <cuda_fp16.h>
#include <math.h>
#include <stdint.h>

__device__ int g_tile_counter;   // reset to 0 by kernel_launch each call

namespace {

constexpr int Bc = 32, Nc = 96, Dc = 32, Fc = 16;
constexpr int THREADS = 640;        // five independent 128-thread streams
constexpr int SWIDTH  = 128;
constexpr int NSTREAM = 5;
constexpr int GRID    = 152;        // persistent: 1 CTA per SM
constexpr int NTILES  = Bc * Nc;    // 3072
constexpr int NSTREAMS_TOTAL = GRID * NSTREAM;   // 760
constexpr int EPAD    = 12;         // u32 words per E row (16 fp16 = 8 words + 4 pad)

// Shared (read-only after init)
constexpr int OFF_WFRAG = 0;                 // uint2[128 nt][32 lane] = 32768
constexpr int OFF_BIAS  = 32768;             // 1024 f = 4096
constexpr int OFF_WIH   = 36864;             // w_ih^T [32][96] = 12288
constexpr int OFF_WHH   = 49152;             // w_hh^T [32][96] = 12288
// Per-stream block
constexpr int OFF_S0  = 61440;
constexpr int SO_E    = 0;       // 96 x 12 u32 = 4608
constexpr int SO_MN   = 4608;    // 1536 float2 = 12288
constexpr int SO_ACT  = 16896;   // [2][96] int = 768 (parity double-buffer)
constexpr int SO_X1   = 17664;   // [2][32] f = 256
constexpr int SO_META = 17920;   // cnt[2], tile[2]
constexpr int SO_AGG  = 17952;   // [2][32] f = 256
constexpr int SO_GI   = 18208;   // 96 f
constexpr int SO_GH   = 18592;   // 96 f
constexpr int SO_H1   = 18976;   // 32 f -> 19104
constexpr int S_BYTES = 19200;
constexpr int SMEM_BYTES = OFF_S0 + NSTREAM * S_BYTES;   // 157440

__device__ __forceinline__ float sigmoidf_(float x) { return 1.0f / (1.0f + expf(-x)); }

__device__ __forceinline__ uint32_t pack_h2(float lo, float hi) {
    const __half2 h = __float22half2_rn(make_float2(lo, hi));   // .x = lo
    return *reinterpret_cast<const uint32_t*>(&h);
}

// fp16 m16n8k16 MMA, f32 accumulate (A row-major, B col-major).
__device__ __forceinline__ void mma_f16(float& d0, float& d1, float& d2, float& d3,
                                        uint32_t a0, uint32_t a1, uint32_t a2, uint32_t a3,
                                        uint32_t b0, uint32_t b1) {
    asm volatile(
        "mma.sync.aligned.m16n8k16.row.col.f32.f16.f16.f32 "
        "{%0,%1,%2,%3}, {%4,%5,%6,%7}, {%8,%9}, {%0,%1,%2,%3};"
        : "+f"(d0), "+f"(d1), "+f"(d2), "+f"(d3)
        : "r"(a0), "r"(a1), "r"(a2), "r"(a3), "r"(b0), "r"(b1));
}

// mn storage: (e,qp) -> float2 slot = ((qp>>2)*12 + (e>>3))*32 + (qp&3)*8 + (e&7)
__device__ __forceinline__ int mn_idx(int e, int qp) {
    return (((qp >> 2) * 12 + (e >> 3)) << 5) + ((qp & 3) << 3) + (e & 7);
}

__device__ __forceinline__ void stream_bar(int s) {
    asm volatile("bar.sync %0, %1;" :: "r"(s + 1), "r"(SWIDTH) : "memory");
}

// Warp-collective: compact active edges of tile t into slot p; stage x1.
__device__ __forceinline__ void compact_tile(int t, int p, int lane,
                                             const float* __restrict__ mask,
                                             const float* __restrict__ nodes,
                                             int* act_sh, int* cnt_sh, float* x1_sh) {
    const int b = t / Nc;
    const int i = t - b * Nc;
    const size_t mbase = (size_t)b * (Nc * Nc) + (size_t)i * Nc;
    int cnt = 0;
#pragma unroll
    for (int rr = 0; rr < Nc / 32; rr++) {
        const int j = rr * 32 + lane;
        const bool a = (mask[mbase + j] != 0.0f);
        const unsigned bal = __ballot_sync(0xffffffffu, a);
        if (a) act_sh[p * 96 + cnt + __popc(bal & ((1u << lane) - 1u))] = j;
        cnt += __popc(bal);
    }
    if (lane == 0) cnt_sh[p] = cnt;
    x1_sh[p * 32 + lane] = nodes[((size_t)b * Nc + i) * Dc + lane];
}

// Warp-collective GRU for one tile (warp 3 of each stream only).
__device__ __forceinline__ void gru_tile(int ptile, int lane,
                                         const float* x1p, const float* aggp,
                                         float* gi_sh, float* gh_sh, float* h1_sh,
                                         const float* wihT, const float* whhT,
                                         const float* __restrict__ b_ih,
                                         const float* __restrict__ b_hh,
                                         float* __restrict__ out) {
    const int pb = ptile / Nc;
    const int pi = ptile - pb * Nc;
#pragma unroll
    for (int g3 = 0; g3 < 3; g3++) {
        const int gate = g3 * 32 + lane;
        float g = b_ih[gate];
#pragma unroll
        for (int d = 0; d < Dc; d++) g = fmaf(x1p[d], wihT[d * 96 + gate], g);
        gi_sh[gate] = g;
    }
    __syncwarp();
    {
        const float r = sigmoidf_(gi_sh[lane] + b_hh[lane]);
        const float z = sigmoidf_(gi_sh[32 + lane] + b_hh[32 + lane]);
        const float n = tanhf(gi_sh[64 + lane] + r * b_hh[64 + lane]);
        h1_sh[lane] = (1.0f - z) * n;   // + z*h0, h0 = 0
    }
    __syncwarp();
#pragma unroll
    for (int g3 = 0; g3 < 3; g3++) {
        const int gate = g3 * 32 + lane;
        float g  = b_ih[gate];
        float gh = b_hh[gate];
#pragma unroll
        for (int d = 0; d < Dc; d++) {
            g  = fmaf(aggp[d],  wihT[d * 96 + gate], g);
            gh = fmaf(h1_sh[d], whhT[d * 96 + gate], gh);
        }
        gi_sh[gate] = g;
        gh_sh[gate] = gh;
    }
    __syncwarp();
    {
        const float r = sigmoidf_(gi_sh[lane] + gh_sh[lane]);
        const float z = sigmoidf_(gi_sh[32 + lane] + gh_sh[32 + lane]);
        const float n = tanhf(gi_sh[64 + lane] + r * gh_sh[64 + lane]);
        out[((size_t)pb * Nc + pi) * Dc + lane] = (1.0f - z) * n + z * h1_sh[lane];
    }
}

__global__ __launch_bounds__(THREADS, 1)
void mp_layer_kernel(const float* __restrict__ nodes,   // [B, N, D]
                     const float* __restrict__ edges,   // [B, N*N, F]
                     const float* __restrict__ mask,    // [B, N*N, 1] (0/1)
                     const float* __restrict__ W_agg,   // [F, D*D]
                     const float* __restrict__ b_agg,   // [D*D]
                     const float* __restrict__ w_ih,    // [3D, D]
                     const float* __restrict__ w_hh,    // [3D, D]
                     const float* __restrict__ b_ih,    // [3D]
                     const float* __restrict__ b_hh,    // [3D]
                     float* __restrict__ out)           // [B, N, D]
{
    extern __shared__ char smem[];
    uint2*  wfrag2  = reinterpret_cast<uint2*>(smem + OFF_WFRAG);
    float*  bias_sh = reinterpret_cast<float*>(smem + OFF_BIAS);
    float*  wihT    = reinterpret_cast<float*>(smem + OFF_WIH);
    float*  whhT    = reinterpret_cast<float*>(smem + OFF_WHH);

    const int tid = threadIdx.x;

    // ---- One-time per CTA: W fragments (fp16x2 pairs: b0={W[2t],W[2t+1]},
    //      b1={W[2t+8],W[2t+9]} at col = nt*8 + lane/4), bias, GRU weights ----
    for (int idx = tid; idx < 128 * 32; idx += THREADS) {
        const int l  = idx & 31;
        const int nt = idx >> 5;
        const int col = nt * 8 + (l >> 2);
        const int t2  = (l & 3) * 2;
        uint2 v;
        v.x = pack_h2(W_agg[(t2)     * 1024 + col], W_agg[(t2 + 1) * 1024 + col]);
        v.y = pack_h2(W_agg[(t2 + 8) * 1024 + col], W_agg[(t2 + 9) * 1024 + col]);
        wfrag2[idx] = v;
    }
    for (int c = tid; c < 1024; c += THREADS) bias_sh[c] = b_agg[c];
    for (int idx = tid; idx < 96 * 32; idx += THREADS) {
        const int g = idx >> 5;
        const int d = idx & 31;
        wihT[d * 96 + g] = w_ih[idx];
        whhT[d * 96 + g] = w_hh[idx];
    }
    __syncthreads();

    // ---- Stream-local views ----
    const int s    = tid >> 7;          // stream 0..4
    const int tids = tid & (SWIDTH - 1);
    const int lane = tid & 31;
    const int wq   = (tid >> 5) & 3;

    char* sbase = smem + OFF_S0 + s * S_BYTES;
    uint32_t* E_sh   = reinterpret_cast<uint32_t*>(sbase + SO_E);
    float2*   mnS    = reinterpret_cast<float2*>(sbase + SO_MN);
    int*      act_sh = reinterpret_cast<int*>(sbase + SO_ACT);
    float*    x1_sh  = reinterpret_cast<float*>(sbase + SO_X1);
    int*      cnt_sh = reinterpret_cast<int*>(sbase + SO_META);
    int*      tile_sh= reinterpret_cast<int*>(sbase + SO_META) + 2;
    float*    agg_sh = reinterpret_cast<float*>(sbase + SO_AGG);
    float*    gi_sh  = reinterpret_cast<float*>(sbase + SO_GI);
    float*    gh_sh  = reinterpret_cast<float*>(sbase + SO_GH);
    float*    h1_sh  = reinterpret_cast<float*>(sbase + SO_H1);

    const int gsid = blockIdx.x * NSTREAM + s;

    // ---- Prefetch: warp 3 compacts the stream's static first tile ----
    if (wq == 3) {
        if (lane == 0) tile_sh[0] = gsid;
        compact_tile(gsid, 0, lane, mask, nodes, act_sh, cnt_sh, x1_sh);
    }
    stream_bar(s);

    // Lane constants for the mainloop
    const int l4   = lane & 3;
    const int lr   = lane >> 2;
    const int mnlo = (l4 << 3) + (lr & 7);

    // ---- Dynamic pipelined tile loop ----
    int it = 0;
    while (true) {
        const int par = it & 1;
        const int cur = tile_sh[par];
        if (cur >= NTILES) break;                 // stream-uniform

        const int b = cur / Nc;
        const int i = cur - b * Nc;
        const size_t ebase = ((size_t)b * (Nc * Nc) + (size_t)i * Nc) * Fc;
        const size_t nbase = (size_t)b * (Nc * Dc);
        const int cnt    = cnt_sh[par];
        const int mtiles = (cnt + 15) >> 4;
        const int padcnt = mtiles << 4;

        if (wq < 3) {
            // Warps 0-2: stage E_act as packed fp16 (zero-padded rows) and mn.
            const int* act = act_sh + par * 96;
            for (int idx = tids; idx < padcnt * 4; idx += 96) {
                const int a  = idx >> 2;
                const int f4 = (idx & 3) << 2;
                uint2 o = make_uint2(0u, 0u);
                if (a < cnt) {
                    const float4 v = *reinterpret_cast<const float4*>(
                        edges + ebase + (size_t)act[a] * Fc + f4);
                    o.x = pack_h2(v.x, v.y);
                    o.y = pack_h2(v.z, v.w);
                }
                *reinterpret_cast<uint2*>(E_sh + a * EPAD + (f4 >> 1)) = o;
            }
            for (int idx = tids; idx < padcnt * 8; idx += 96) {
                const int a  = idx >> 3;
                const int q2 = (idx & 7) << 1;    // qp pair: q2, q2+1
                float4 v = make_float4(0.f, 0.f, 0.f, 0.f);
                if (a < cnt) {
                    v = *reinterpret_cast<const float4*>(
                        nodes + nbase + (size_t)act[a] * Dc + q2 * 2);
                }
                mnS[mn_idx(a, q2)]     = make_float2(v.x, v.y);
                mnS[mn_idx(a, q2 + 1)] = make_float2(v.z, v.w);
            }
        } else {
            // Warp 3: GRU(previous tile), then grab + compact next.
            if (it > 0) {
                const int pp = (it - 1) & 1;
                gru_tile(tile_sh[pp], lane, x1_sh + pp * 32, agg_sh + pp * 32,
                         gi_sh, gh_sh, h1_sh, wihT, whhT, b_ih, b_hh, out);
            }
            int nxt;
            if (lane == 0) nxt = NSTREAMS_TOTAL + atomicAdd(&g_tile_counter, 1);
            nxt = __shfl_sync(0xffffffffu, nxt, 0);
            const int np = (it + 1) & 1;
            if (lane == 0) tile_sh[np] = nxt;
            if (nxt < NTILES)
                compact_tile(nxt, np, lane, mask, nodes, act_sh, cnt_sh, x1_sh);
        }
        stream_bar(s);   // staging done, GRU done, next tile compacted

        // ---- MMA + fused epilogue (all 4 warps); PAIR-blocked m loop.
        //      One fp16 m16n8k16 MMA covers the full K=16 per n-tile/m-block. ----
        float acc[8] = {0.f, 0.f, 0.f, 0.f, 0.f, 0.f, 0.f, 0.f};

        int mt = 0;
        for (; mt + 2 <= mtiles; mt += 2) {
            const int r0 = mt * 16 + lr;
            const uint32_t* e0p = E_sh + r0 * EPAD;
            // Block A (rows r0, r0+8), block B (rows r0+16, r0+24).
            const uint32_t a00 = e0p[l4],        a01 = e0p[96 + l4];
            const uint32_t a02 = e0p[l4 + 4],    a03 = e0p[96 + l4 + 4];
            const uint32_t b00 = e0p[192 + l4],  b01 = e0p[288 + l4];
            const uint32_t b02 = e0p[192 + l4 + 4], b03 = e0p[288 + l4 + 4];
            const int blk0 = mt * 2;

#pragma unroll
            for (int c = 0; c < 4; c++) {
                const float2* mp = mnS + ((c * 12 + blk0) << 5) + mnlo;
                const float2 m0 = mp[0];
                const float2 m1 = mp[32];
                const float2 m2 = mp[64];
                const float2 m3 = mp[96];
                const uint2* wp = wfrag2 + (wq * 32 + c) * 32 + lane;
                const float2* bp = reinterpret_cast<const float2*>(
                    bias_sh + wq * 256 + c * 8 + l4 * 2);
#pragma unroll
                for (int tsub = 0; tsub < 8; tsub++) {
                    const uint2 wf = *wp;   wp += 128;
                    const float2 bb = *bp;  bp += 16;
                    float d0 = bb.x, d1 = bb.y, d2 = bb.x, d3 = bb.y;
                    float f0 = bb.x, f1 = bb.y, f2 = bb.x, f3 = bb.y;
                    mma_f16(d0, d1, d2, d3, a00, a01, a02, a03, wf.x, wf.y);
                    mma_f16(f0, f1, f2, f3, b00, b01, b02, b03, wf.x, wf.y);
                    d0 = fmaxf(d0, 0.0f); d1 = fmaxf(d1, 0.0f);
                    d2 = fmaxf(d2, 0.0f); d3 = fmaxf(d3, 0.0f);
                    f0 = fmaxf(f0, 0.0f); f1 = fmaxf(f1, 0.0f);
                    f2 = fmaxf(f2, 0.0f); f3 = fmaxf(f3, 0.0f);
                    float v = fmaf(d0, m0.x, fmaf(d1, m0.y,
                              fmaf(d2, m1.x, fmaf(d3, m1.y, acc[tsub]))));
                    acc[tsub] = fmaf(f0, m2.x, fmaf(f1, m2.y,
                                fmaf(f2, m3.x, fmaf(f3, m3.y, v))));
                }
            }
        }
        if (mt < mtiles) {   // single-block tail (odd mtiles)
            const int r0 = mt * 16 + lr;
            const uint32_t* e0p = E_sh + r0 * EPAD;
            const uint32_t a00 = e0p[l4],     a01 = e0p[96 + l4];
            const uint32_t a02 = e0p[l4 + 4], a03 = e0p[96 + l4 + 4];
            const int blk0 = mt * 2;
#pragma unroll
            for (int c = 0; c < 4; c++) {
                const float2* mp = mnS + ((c * 12 + blk0) << 5) + mnlo;
                const float2 m0 = mp[0];
                const float2 m1 = mp[32];
                const uint2* wp = wfrag2 + (wq * 32 + c) * 32 + lane;
                const float2* bp = reinterpret_cast<const float2*>(
                    bias_sh + wq * 256 + c * 8 + l4 * 2);
#pragma unroll
                for (int tsub = 0; tsub < 8; tsub++) {
                    const uint2 wf = *wp;   wp += 128;
                    const float2 bb = *bp;  bp += 16;
                    float d0 = bb.x, d1 = bb.y, d2 = bb.x, d3 = bb.y;
                    mma_f16(d0, d1, d2, d3, a00, a01, a02, a03, wf.x, wf.y);
                    d0 = fmaxf(d0, 0.0f); d1 = fmaxf(d1, 0.0f);
                    d2 = fmaxf(d2, 0.0f); d3 = fmaxf(d3, 0.0f);
                    acc[tsub] = fmaf(d0, m0.x, fmaf(d1, m0.y,
                                fmaf(d2, m1.x, fmaf(d3, m1.y, acc[tsub]))));
                }
            }
        }

        // Warp-reduce the 8 p-accumulators -> agg_sh[par][wq*8 + pi]
#pragma unroll
        for (int pi = 0; pi < 8; pi++) {
            float v = acc[pi];
#pragma unroll
            for (int o = 16; o; o >>= 1) v += __shfl_xor_sync(0xffffffffu, v, o);
            if (lane == 0) agg_sh[par * 32 + wq * 8 + pi] = v;
        }
        stream_bar(s);   // agg ready; E/mn free; tile_sh[next] visible
        it++;
    }

    // ---- Drain: GRU for the last processed tile ----
    if (wq == 3 && it > 0) {
        const int pp = (it - 1) & 1;
        gru_tile(tile_sh[pp], lane, x1_sh + pp * 32, agg_sh + pp * 32,
                 gi_sh, gh_sh, h1_sh, wihT, whhT, b_ih, b_hh, out);
    }
}

} // namespace

extern "C" void kernel_launch(void* const* d_in, const int* in_sizes, int n_in,
                              void* d_out, int out_size) {
    const float* nodes = (const float*)d_in[0];
    const float* edges = (const float*)d_in[1];
    const float* mask  = (const float*)d_in[2];
    const float* W_agg = (const float*)d_in[3];
    const float* b_agg = (const float*)d_in[4];
    const float* w_ih  = (const float*)d_in[5];
    const float* w_hh  = (const float*)d_in[6];
    const float* b_ih  = (const float*)d_in[7];
    const float* b_hh  = (const float*)d_in[8];
    float* out = (float*)d_out;

    void* ctr = nullptr;
    cudaGetSymbolAddress(&ctr, g_tile_counter);
    cudaMemsetAsync(ctr, 0, sizeof(int));

    cudaFuncSetAttribute(mp_layer_kernel,
                         cudaFuncAttributeMaxDynamicSharedMemorySize, SMEM_BYTES);
    mp_layer_kernel<<<GRID, THREADS, SMEM_BYTES>>>(nodes, edges, mask, W_agg, b_agg,
                                                   w_ih, w_hh, b_ih, b_hh, out);
}

// round 17
// speedup vs baseline: 1.3928x; 1.1027x over previous
#include <cuda_runtime.h>
#include <cuda_fp16.h>
#include <math.h>
#include <stdint.h>

__device__ int g_tile_counter;   // reset to 0 by kernel_launch each call

namespace {

constexpr int Bc = 32, Nc = 96, Dc = 32, Fc = 16;
constexpr int THREADS = 640;        // five independent 128-thread streams
constexpr int SWIDTH  = 128;
constexpr int NSTREAM = 5;
constexpr int GRID    = 152;        // persistent: 1 CTA per SM
constexpr int NTILES  = Bc * Nc;    // 3072
constexpr int NSTREAMS_TOTAL = GRID * NSTREAM;   // 760
constexpr int EPAD    = 12;         // u32 words per E row (16 fp16 = 8 words + 4 pad)

// Shared (read-only after init)
constexpr int OFF_WFRAG = 0;                 // uint2[128 nt][32 lane] = 32768
constexpr int OFF_BIAS  = 32768;             // 1024 f = 4096
constexpr int OFF_WIH   = 36864;             // w_ih^T [32][96] = 12288
constexpr int OFF_WHH   = 49152;             // w_hh^T [32][96] = 12288
// Per-stream block
constexpr int OFF_S0  = 61440;
constexpr int SO_E    = 0;       // 96 x 12 u32 = 4608
constexpr int SO_MN   = 4608;    // 1536 float2 = 12288 -> 16896
constexpr int SO_ACT  = 16896;   // [4][96] int = 1536  -> 18432
constexpr int SO_X1   = 18432;   // [4][32] f = 512     -> 18944
constexpr int SO_CNT  = 18944;   // [4] int             -> 18960
constexpr int SO_TILE = 18960;   // [4] int             -> 18976
constexpr int SO_AGG  = 18976;   // [2][32] f = 256     -> 19232
constexpr int SO_GI   = 19232;   // 96 f (gi1)          -> 19616
constexpr int SO_GI2  = 19616;   // 96 f (gi2)          -> 20000
constexpr int SO_GH   = 20000;   // 96 f (gh2)          -> 20384
constexpr int SO_H1   = 20384;   // 32 f                -> 20512
constexpr int S_BYTES = 20608;
constexpr int SMEM_BYTES = OFF_S0 + NSTREAM * S_BYTES;   // 164480

__device__ __forceinline__ float sigmoidf_(float x) { return 1.0f / (1.0f + expf(-x)); }

__device__ __forceinline__ uint32_t pack_h2(float lo, float hi) {
    const __half2 h = __float22half2_rn(make_float2(lo, hi));   // .x = lo
    return *reinterpret_cast<const uint32_t*>(&h);
}

// fp16 m16n8k16 MMA, f32 accumulate (A row-major, B col-major).
__device__ __forceinline__ void mma_f16(float& d0, float& d1, float& d2, float& d3,
                                        uint32_t a0, uint32_t a1, uint32_t a2, uint32_t a3,
                                        uint32_t b0, uint32_t b1) {
    asm volatile(
        "mma.sync.aligned.m16n8k16.row.col.f32.f16.f16.f32 "
        "{%0,%1,%2,%3}, {%4,%5,%6,%7}, {%8,%9}, {%0,%1,%2,%3};"
        : "+f"(d0), "+f"(d1), "+f"(d2), "+f"(d3)
        : "r"(a0), "r"(a1), "r"(a2), "r"(a3), "r"(b0), "r"(b1));
}

// mn storage: (e,qp) -> float2 slot = ((qp>>2)*12 + (e>>3))*32 + (qp&3)*8 + (e&7)
__device__ __forceinline__ int mn_idx(int e, int qp) {
    return (((qp >> 2) * 12 + (e >> 3)) << 5) + ((qp & 3) << 3) + (e & 7);
}

__device__ __forceinline__ void stream_bar(int s) {
    asm volatile("bar.sync %0, %1;" :: "r"(s + 1), "r"(SWIDTH) : "memory");
}
// 64-thread barrier shared by warps 2 and 3 of one stream (ids 6..10).
__device__ __forceinline__ void gru_bar(int s) {
    asm volatile("bar.sync %0, %1;" :: "r"(s + 6), "r"(64) : "memory");
}

// Warp-collective: compact active edges of tile t into slot p; stage x1.
__device__ __forceinline__ void compact_tile(int t, int p, int lane,
                                             const float* __restrict__ mask,
                                             const float* __restrict__ nodes,
                                             int* act_sh, int* cnt_sh, float* x1_sh) {
    const int b = t / Nc;
    const int i = t - b * Nc;
    const size_t mbase = (size_t)b * (Nc * Nc) + (size_t)i * Nc;
    int cnt = 0;
#pragma unroll
    for (int rr = 0; rr < Nc / 32; rr++) {
        const int j = rr * 32 + lane;
        const bool a = (mask[mbase + j] != 0.0f);
        const unsigned bal = __ballot_sync(0xffffffffu, a);
        if (a) act_sh[p * 96 + cnt + __popc(bal & ((1u << lane) - 1u))] = j;
        cnt += __popc(bal);
    }
    if (lane == 0) cnt_sh[p] = cnt;
    x1_sh[p * 32 + lane] = nodes[((size_t)b * Nc + i) * Dc + lane];
}

// Solo (warp 3) full GRU — drain path only.
__device__ __forceinline__ void gru_tile_solo(int ptile, int lane,
                                              const float* x1p, const float* aggp,
                                              float* gi_sh, float* gh_sh, float* h1_sh,
                                              const float* wihT, const float* whhT,
                                              const float* __restrict__ b_ih,
                                              const float* __restrict__ b_hh,
                                              float* __restrict__ out) {
    const int pb = ptile / Nc;
    const int pi = ptile - pb * Nc;
#pragma unroll
    for (int g3 = 0; g3 < 3; g3++) {
        const int gate = g3 * 32 + lane;
        float g = b_ih[gate];
#pragma unroll
        for (int d = 0; d < Dc; d++) g = fmaf(x1p[d], wihT[d * 96 + gate], g);
        gi_sh[gate] = g;
    }
    __syncwarp();
    {
        const float r = sigmoidf_(gi_sh[lane] + b_hh[lane]);
        const float z = sigmoidf_(gi_sh[32 + lane] + b_hh[32 + lane]);
        const float n = tanhf(gi_sh[64 + lane] + r * b_hh[64 + lane]);
        h1_sh[lane] = (1.0f - z) * n;   // + z*h0, h0 = 0
    }
    __syncwarp();
#pragma unroll
    for (int g3 = 0; g3 < 3; g3++) {
        const int gate = g3 * 32 + lane;
        float g  = b_ih[gate];
        float gh = b_hh[gate];
#pragma unroll
        for (int d = 0; d < Dc; d++) {
            g  = fmaf(aggp[d],  wihT[d * 96 + gate], g);
            gh = fmaf(h1_sh[d], whhT[d * 96 + gate], gh);
        }
        gi_sh[gate] = g;
        gh_sh[gate] = gh;
    }
    __syncwarp();
    {
        const float r = sigmoidf_(gi_sh[lane] + gh_sh[lane]);
        const float z = sigmoidf_(gi_sh[32 + lane] + gh_sh[32 + lane]);
        const float n = tanhf(gi_sh[64 + lane] + r * gh_sh[64 + lane]);
        out[((size_t)pb * Nc + pi) * Dc + lane] = (1.0f - z) * n + z * h1_sh[lane];
    }
}

__global__ __launch_bounds__(THREADS, 1)
void mp_layer_kernel(const float* __restrict__ nodes,   // [B, N, D]
                     const float* __restrict__ edges,   // [B, N*N, F]
                     const float* __restrict__ mask,    // [B, N*N, 1] (0/1)
                     const float* __restrict__ W_agg,   // [F, D*D]
                     const float* __restrict__ b_agg,   // [D*D]
                     const float* __restrict__ w_ih,    // [3D, D]
                     const float* __restrict__ w_hh,    // [3D, D]
                     const float* __restrict__ b_ih,    // [3D]
                     const float* __restrict__ b_hh,    // [3D]
                     float* __restrict__ out)           // [B, N, D]
{
    extern __shared__ char smem[];
    uint2*  wfrag2  = reinterpret_cast<uint2*>(smem + OFF_WFRAG);
    float*  bias_sh = reinterpret_cast<float*>(smem + OFF_BIAS);
    float*  wihT    = reinterpret_cast<float*>(smem + OFF_WIH);
    float*  whhT    = reinterpret_cast<float*>(smem + OFF_WHH);

    const int tid = threadIdx.x;

    // ---- One-time per CTA: W fragments (fp16), bias, transposed GRU weights ----
    for (int idx = tid; idx < 128 * 32; idx += THREADS) {
        const int l  = idx & 31;
        const int nt = idx >> 5;
        const int col = nt * 8 + (l >> 2);
        const int t2  = (l & 3) * 2;
        uint2 v;
        v.x = pack_h2(W_agg[(t2)     * 1024 + col], W_agg[(t2 + 1) * 1024 + col]);
        v.y = pack_h2(W_agg[(t2 + 8) * 1024 + col], W_agg[(t2 + 9) * 1024 + col]);
        wfrag2[idx] = v;
    }
    for (int c = tid; c < 1024; c += THREADS) bias_sh[c] = b_agg[c];
    for (int idx = tid; idx < 96 * 32; idx += THREADS) {
        const int g = idx >> 5;
        const int d = idx & 31;
        wihT[d * 96 + g] = w_ih[idx];
        whhT[d * 96 + g] = w_hh[idx];
    }
    __syncthreads();

    // ---- Stream-local views ----
    const int s    = tid >> 7;          // stream 0..4
    const int lane = tid & 31;
    const int wq   = (tid >> 5) & 3;

    char* sbase = smem + OFF_S0 + s * S_BYTES;
    uint32_t* E_sh   = reinterpret_cast<uint32_t*>(sbase + SO_E);
    float2*   mnS    = reinterpret_cast<float2*>(sbase + SO_MN);
    int*      act_sh = reinterpret_cast<int*>(sbase + SO_ACT);
    float*    x1_sh  = reinterpret_cast<float*>(sbase + SO_X1);
    int*      cnt_sh = reinterpret_cast<int*>(sbase + SO_CNT);
    int*      tile_sh= reinterpret_cast<int*>(sbase + SO_TILE);
    float*    agg_sh = reinterpret_cast<float*>(sbase + SO_AGG);
    float*    gi_sh  = reinterpret_cast<float*>(sbase + SO_GI);
    float*    gi2_sh = reinterpret_cast<float*>(sbase + SO_GI2);
    float*    gh_sh  = reinterpret_cast<float*>(sbase + SO_GH);
    float*    h1_sh  = reinterpret_cast<float*>(sbase + SO_H1);

    const int gsid = blockIdx.x * NSTREAM + s;

    // ---- Prefetch: warp 3 compacts the stream's static first tile ----
    if (wq == 3) {
        if (lane == 0) tile_sh[0] = gsid;
        compact_tile(gsid, 0, lane, mask, nodes, act_sh, cnt_sh, x1_sh);
    }
    stream_bar(s);

    // Lane constants for the mainloop
    const int l4   = lane & 3;
    const int lr   = lane >> 2;
    const int mnlo = (l4 << 3) + (lr & 7);

    // ---- Dynamic pipelined tile loop ----
    int it = 0;
    while (true) {
        const int slot = it & 3;
        const int par  = it & 1;
        const int cur  = tile_sh[slot];
        if (cur >= NTILES) break;                 // stream-uniform

        const int b = cur / Nc;
        const int i = cur - b * Nc;
        const size_t ebase = ((size_t)b * (Nc * Nc) + (size_t)i * Nc) * Fc;
        const size_t nbase = (size_t)b * (Nc * Dc);
        const int cnt    = cnt_sh[slot];
        const int mtiles = (cnt + 15) >> 4;
        const int padcnt = mtiles << 4;
        const bool pv = (it > 0);   // prev tile valid (was cur of it-1)

        // ================= Overlap phase (split by warp) =================
        if (wq == 0) {
            // Stage E_act as packed fp16 (zero-padded rows).
            const int* act = act_sh + slot * 96;
            for (int idx = lane; idx < padcnt * 4; idx += 32) {
                const int a  = idx >> 2;
                const int f4 = (idx & 3) << 2;
                uint2 o = make_uint2(0u, 0u);
                if (a < cnt) {
                    const float4 v = *reinterpret_cast<const float4*>(
                        edges + ebase + (size_t)act[a] * Fc + f4);
                    o.x = pack_h2(v.x, v.y);
                    o.y = pack_h2(v.z, v.w);
                }
                *reinterpret_cast<uint2*>(E_sh + a * EPAD + (f4 >> 1)) = o;
            }
        } else if (wq == 1) {
            // Stage mn (zero-padded).
            const int* act = act_sh + slot * 96;
            for (int idx = lane; idx < padcnt * 8; idx += 32) {
                const int a  = idx >> 3;
                const int q2 = (idx & 7) << 1;
                float4 v = make_float4(0.f, 0.f, 0.f, 0.f);
                if (a < cnt) {
                    v = *reinterpret_cast<const float4*>(
                        nodes + nbase + (size_t)act[a] * Dc + q2 * 2);
                }
                mnS[mn_idx(a, q2)]     = make_float2(v.x, v.y);
                mnS[mn_idx(a, q2 + 1)] = make_float2(v.z, v.w);
            }
        } else if (wq == 2) {
            // Compact next tile, then GRU part A (gi2 + gh2 gates 0-31,64-95).
            const int nslot = (it + 1) & 3;
            int nxt;
            if (lane == 0) nxt = NSTREAMS_TOTAL + atomicAdd(&g_tile_counter, 1);
            nxt = __shfl_sync(0xffffffffu, nxt, 0);
            if (lane == 0) tile_sh[nslot] = nxt;
            if (nxt < NTILES)
                compact_tile(nxt, nslot, lane, mask, nodes, act_sh, cnt_sh, x1_sh);
            if (pv) {
                const float* aggp = agg_sh + ((it - 1) & 1) * 32;
#pragma unroll
                for (int g3 = 0; g3 < 3; g3++) {
                    const int gate = g3 * 32 + lane;
                    float g = b_ih[gate];
#pragma unroll
                    for (int d = 0; d < Dc; d++)
                        g = fmaf(aggp[d], wihT[d * 96 + gate], g);
                    gi2_sh[gate] = g;
                }
                gru_bar(s);   // publish gi2; wait for h1
#pragma unroll
                for (int gg = 0; gg < 2; gg++) {
                    const int gate = lane + gg * 64;   // 0-31, 64-95
                    float gh = b_hh[gate];
#pragma unroll
                    for (int d = 0; d < Dc; d++)
                        gh = fmaf(h1_sh[d], whhT[d * 96 + gate], gh);
                    gh_sh[gate] = gh;
                }
                gru_bar(s);
            }
        } else {
            // Warp 3: GRU part B (gi1 -> h1 -> gh2 gates 32-63 -> output).
            if (pv) {
                const int prev = tile_sh[(it - 1) & 3];
                const float* x1p = x1_sh + ((it - 1) & 3) * 32;
#pragma unroll
                for (int g3 = 0; g3 < 3; g3++) {
                    const int gate = g3 * 32 + lane;
                    float g = b_ih[gate];
#pragma unroll
                    for (int d = 0; d < Dc; d++)
                        g = fmaf(x1p[d], wihT[d * 96 + gate], g);
                    gi_sh[gate] = g;
                }
                __syncwarp();
                {
                    const float r = sigmoidf_(gi_sh[lane] + b_hh[lane]);
                    const float z = sigmoidf_(gi_sh[32 + lane] + b_hh[32 + lane]);
                    const float n = tanhf(gi_sh[64 + lane] + r * b_hh[64 + lane]);
                    h1_sh[lane] = (1.0f - z) * n;   // + z*h0, h0 = 0
                }
                __syncwarp();
                gru_bar(s);   // publish h1; wait for gi2
                {
                    const int gate = 32 + lane;
                    float gh = b_hh[gate];
#pragma unroll
                    for (int d = 0; d < Dc; d++)
                        gh = fmaf(h1_sh[d], whhT[d * 96 + gate], gh);
                    gh_sh[gate] = gh;
                }
                gru_bar(s);   // gh2 complete
                {
                    const int pb = prev / Nc;
                    const int pi = prev - pb * Nc;
                    const float r = sigmoidf_(gi2_sh[lane] + gh_sh[lane]);
                    const float z = sigmoidf_(gi2_sh[32 + lane] + gh_sh[32 + lane]);
                    const float n = tanhf(gi2_sh[64 + lane] + r * gh_sh[64 + lane]);
                    out[((size_t)pb * Nc + pi) * Dc + lane] =
                        (1.0f - z) * n + z * h1_sh[lane];
                }
            }
        }
        stream_bar(s);   // staging + GRU + compact all done

        // ================= MMA + fused epilogue (all 4 warps) =================
        float acc[8] = {0.f, 0.f, 0.f, 0.f, 0.f, 0.f, 0.f, 0.f};

        int mt = 0;
        for (; mt + 2 <= mtiles; mt += 2) {
            const int r0 = mt * 16 + lr;
            const uint32_t* e0p = E_sh + r0 * EPAD;
            const uint32_t a00 = e0p[l4],        a01 = e0p[96 + l4];
            const uint32_t a02 = e0p[l4 + 4],    a03 = e0p[96 + l4 + 4];
            const uint32_t b00 = e0p[192 + l4],  b01 = e0p[288 + l4];
            const uint32_t b02 = e0p[192 + l4 + 4], b03 = e0p[288 + l4 + 4];
            const int blk0 = mt * 2;

#pragma unroll
            for (int c = 0; c < 4; c++) {
                const float2* mp = mnS + ((c * 12 + blk0) << 5) + mnlo;
                const float2 m0 = mp[0];
                const float2 m1 = mp[32];
                const float2 m2 = mp[64];
                const float2 m3 = mp[96];
                const uint2* wp = wfrag2 + (wq * 32 + c) * 32 + lane;
                const float2* bp = reinterpret_cast<const float2*>(
                    bias_sh + wq * 256 + c * 8 + l4 * 2);
#pragma unroll
                for (int tsub = 0; tsub < 8; tsub++) {
                    const uint2 wf = *wp;   wp += 128;
                    const float2 bb = *bp;  bp += 16;
                    float d0 = bb.x, d1 = bb.y, d2 = bb.x, d3 = bb.y;
                    float f0 = bb.x, f1 = bb.y, f2 = bb.x, f3 = bb.y;
                    mma_f16(d0, d1, d2, d3, a00, a01, a02, a03, wf.x, wf.y);
                    mma_f16(f0, f1, f2, f3, b00, b01, b02, b03, wf.x, wf.y);
                    d0 = fmaxf(d0, 0.0f); d1 = fmaxf(d1, 0.0f);
                    d2 = fmaxf(d2, 0.0f); d3 = fmaxf(d3, 0.0f);
                    f0 = fmaxf(f0, 0.0f); f1 = fmaxf(f1, 0.0f);
                    f2 = fmaxf(f2, 0.0f); f3 = fmaxf(f3, 0.0f);
                    float v = fmaf(d0, m0.x, fmaf(d1, m0.y,
                              fmaf(d2, m1.x, fmaf(d3, m1.y, acc[tsub]))));
                    acc[tsub] = fmaf(f0, m2.x, fmaf(f1, m2.y,
                                fmaf(f2, m3.x, fmaf(f3, m3.y, v))));
                }
            }
        }
        if (mt < mtiles) {   // single-block tail (odd mtiles)
            const int r0 = mt * 16 + lr;
            const uint32_t* e0p = E_sh + r0 * EPAD;
            const uint32_t a00 = e0p[l4],     a01 = e0p[96 + l4];
            const uint32_t a02 = e0p[l4 + 4], a03 = e0p[96 + l4 + 4];
            const int blk0 = mt * 2;
#pragma unroll
            for (int c = 0; c < 4; c++) {
                const float2* mp = mnS + ((c * 12 + blk0) << 5) + mnlo;
                const float2 m0 = mp[0];
                const float2 m1 = mp[32];
                const uint2* wp = wfrag2 + (wq * 32 + c) * 32 + lane;
                const float2* bp = reinterpret_cast<const float2*>(
                    bias_sh + wq * 256 + c * 8 + l4 * 2);
#pragma unroll
                for (int tsub = 0; tsub < 8; tsub++) {
                    const uint2 wf = *wp;   wp += 128;
                    const float2 bb = *bp;  bp += 16;
                    float d0 = bb.x, d1 = bb.y, d2 = bb.x, d3 = bb.y;
                    mma_f16(d0, d1, d2, d3, a00, a01, a02, a03, wf.x, wf.y);
                    d0 = fmaxf(d0, 0.0f); d1 = fmaxf(d1, 0.0f);
                    d2 = fmaxf(d2, 0.0f); d3 = fmaxf(d3, 0.0f);
                    acc[tsub] = fmaf(d0, m0.x, fmaf(d1, m0.y,
                                fmaf(d2, m1.x, fmaf(d3, m1.y, acc[tsub]))));
                }
            }
        }

        // Warp-reduce the 8 p-accumulators -> agg_sh[par][wq*8 + pi]
#pragma unroll
        for (int pi = 0; pi < 8; pi++) {
            float v = acc[pi];
#pragma unroll
            for (int o = 16; o; o >>= 1) v += __shfl_xor_sync(0xffffffffu, v, o);
            if (lane == 0) agg_sh[par * 32 + wq * 8 + pi] = v;
        }
        stream_bar(s);   // agg ready; E/mn free; next tile meta visible
        it++;
    }

    // ---- Drain: GRU for the last processed tile (solo warp 3) ----
    if (wq == 3 && it > 0) {
        const int pslot = (it - 1) & 3;
        gru_tile_solo(tile_sh[pslot], lane, x1_sh + pslot * 32,
                      agg_sh + ((it - 1) & 1) * 32,
                      gi_sh, gh_sh, h1_sh, wihT, whhT, b_ih, b_hh, out);
    }
}

} // namespace

extern "C" void kernel_launch(void* const* d_in, const int* in_sizes, int n_in,
                              void* d_out, int out_size) {
    const float* nodes = (const float*)d_in[0];
    const float* edges = (const float*)d_in[1];
    const float* mask  = (const float*)d_in[2];
    const float* W_agg = (const float*)d_in[3];
    const float* b_agg = (const float*)d_in[4];
    const float* w_ih  = (const float*)d_in[5];
    const float* w_hh  = (const float*)d_in[6];
    const float* b_ih  = (const float*)d_in[7];
    const float* b_hh  = (const float*)d_in[8];
    float* out = (float*)d_out;

    void* ctr = nullptr;
    cudaGetSymbolAddress(&ctr, g_tile_counter);
    cudaMemsetAsync(ctr, 0, sizeof(int));

    cudaFuncSetAttribute(mp_layer_kernel,
                         cudaFuncAttributeMaxDynamicSharedMemorySize, SMEM_BYTES);
    mp_layer_kernel<<<GRID, THREADS, SMEM_BYTES>>>(nodes, edges, mask, W_agg, b_agg,
                                                   w_ih, w_hh, b_ih, b_hh, out);
}